// round 10
// baseline (speedup 1.0000x reference)
#include <cuda_runtime.h>
#include <cstdint>

// LIF neuron scan: 2048 serial timesteps over 16384 independent neurons.
// R9: warp-specialized producer/consumer.
//   warps 0-3 (128 threads): compute — one neuron per thread, spikes -> smem.
//   warps 4-7 (128 threads): cp.async issue + wait, and STG.128 of the
//                            previous chunk's staged spikes (overlapped).
// Ring: 5 stages x 32 KB (I+noise). Spike staging: 2 x 16 KB. Total 192 KB.

#define LIF_T 2048
#define LIF_N 16384
#define CHUNK 32
#define STAGES 5
#define NCHUNK (LIF_T / CHUNK)          // 64
#define BN 128                           // neurons per block
#define NTHREADS 256
#define STAGE_FLOATS (2 * CHUNK * BN)    // 8192 floats = 32 KB
#define RING_FLOATS (STAGES * STAGE_FLOATS)
#define SBUF_FLOATS (CHUNK * BN)         // 4096 floats = 16 KB
#define SMEM_BYTES ((RING_FLOATS + 2 * SBUF_FLOATS) * 4)  // 192 KB

__device__ __forceinline__ void cp16(float* dst, const float4* src) {
    uint32_t s = (uint32_t)__cvta_generic_to_shared(dst);
    asm volatile("cp.async.cg.shared.global [%0], [%1], 16;\n"
                 :: "r"(s), "l"(src));
}
__device__ __forceinline__ void cp_commit() {
    asm volatile("cp.async.commit_group;\n" ::: "memory");
}
template <int N>
__device__ __forceinline__ void cp_wait() {
    asm volatile("cp.async.wait_group %0;\n" :: "n"(N) : "memory");
}

// Producer threads (128 of them, ptid = tid-128) issue one stage:
// 2048 float4 ops / 128 threads = 16 cp.async per thread, one commit group.
__device__ __forceinline__ void issue_stage(
    float* __restrict__ ring, int c, int stage,
    const float4* __restrict__ gI4, const float4* __restrict__ gZ4, int ptid)
{
    float* sI = ring + stage * STAGE_FLOATS;
    float* sZ = sI + CHUNK * BN;
#pragma unroll
    for (int k = 0; k < 16; ++k) {
        const int idx = k * 128 + ptid;      // 0..2047 over {I,Z} halves
        const int half = idx >> 10;          // 0 = I, 1 = Z
        const int sub = idx & 1023;
        const int row = sub >> 5;            // 32 float4 per 128-neuron row
        const int col = sub & 31;
        const size_t goff = (size_t)(c * CHUNK + row) * (LIF_N / 4) + col;
        float* sdst = (half ? sZ : sI) + row * BN + col * 4;
        const float4* gsrc = (half ? gZ4 : gI4) + goff;
        cp16(sdst, gsrc);
    }
    cp_commit();
}

// Producer threads store one staged spike chunk (16 KB) as float4.
__device__ __forceinline__ void store_spikes(
    const float* __restrict__ sbuf, float* __restrict__ gOut,
    int c, int blockN, int ptid)
{
    const float4* s4 = (const float4*)sbuf;
#pragma unroll
    for (int k = 0; k < 8; ++k) {
        const int idx = k * 128 + ptid;      // 0..1023
        const int row = idx >> 5;
        const int col = idx & 31;
        float4 v = s4[row * (BN / 4) + col];
        float4* g = (float4*)(gOut + (size_t)(c * CHUNK + row) * LIF_N
                              + blockN + col * 4);
        *g = v;  // write-back: let the 126MB L2 smooth the DRAM write stream
    }
}

__global__ void __launch_bounds__(NTHREADS, 1)
TorchLIFNeuronGroup_kernel(const float* __restrict__ gI,
                           const float* __restrict__ gZ,
                           float* __restrict__ gOut)
{
    extern __shared__ float smem[];
    float* ring = smem;
    float* sbuf0 = smem + RING_FLOATS;
    float* sbuf1 = sbuf0 + SBUF_FLOATS;

    const int tid = threadIdx.x;
    const bool is_producer = (tid >= BN);
    const int ptid = tid - BN;               // producer lane 0..127
    const int blockN = blockIdx.x * BN;

    const float4* gI4 = (const float4*)(gI + blockN);
    const float4* gZ4 = (const float4*)(gZ + blockN);

    // Prologue: producers fill the ring.
    if (is_producer) {
#pragma unroll
        for (int s = 0; s < STAGES; ++s)
            issue_stage(ring, s, s, gI4, gZ4, ptid);
    }

    float V = 0.0f;    // V_RESET
    float Vth = 1.0f;  // V_TH0

    for (int c = 0; c < NCHUNK; ++c) {
        const int stage = c % STAGES;
        float* sb = (c & 1) ? sbuf1 : sbuf0;

        if (is_producer) {
            // Groups pending after stage c's group:
            const int rem = (NCHUNK - 1 - c < STAGES - 1) ? (NCHUNK - 1 - c)
                                                          : (STAGES - 1);
            switch (rem) {
                case 4: cp_wait<4>(); break;
                case 3: cp_wait<3>(); break;
                case 2: cp_wait<2>(); break;
                case 1: cp_wait<1>(); break;
                default: cp_wait<0>(); break;
            }
        }
        __syncthreads();  // A: stage c visible to consumers; sbuf[c&1] free

        if (!is_producer) {
            // Compute CHUNK timesteps (bit-exact R5 body); spikes -> smem.
            const float* sI = ring + stage * STAGE_FLOATS + tid;
            const float* sZ = sI + CHUNK * BN;
#pragma unroll
            for (int u = 0; u < CHUNK; ++u) {
                const float I  = sI[u * BN];
                const float nz = sZ[u * BN];
                // V = V + (DT/TAU)*(I - V) + noise  (reference op order)
                V = __fmaf_rn(0.05f, I - V, V) + nz;
                const bool sp = (V >= Vth);
                sb[u * BN + tid] = sp ? 1.0f : 0.0f;
                V = sp ? 0.0f : V;
                // Vth starts at 1.0, never decreases -> lower clip is a no-op.
                Vth = sp ? Vth + 0.1f : Vth;
                Vth = fminf(Vth, 2.0f);
            }
        } else if (c > 0) {
            // Overlapped with compute: store previous chunk's spikes.
            store_spikes((c & 1) ? sbuf0 : sbuf1, gOut, c - 1, blockN, ptid);
        }
        __syncthreads();  // B: stage c fully read; sbuf[c&1] filled

        if (is_producer && (c + STAGES < NCHUNK))
            issue_stage(ring, c + STAGES, stage, gI4, gZ4, ptid);
    }

    // Epilogue: last chunk's spikes.
    if (is_producer)
        store_spikes(((NCHUNK - 1) & 1) ? sbuf1 : sbuf0, gOut,
                     NCHUNK - 1, blockN, ptid);
}

extern "C" void kernel_launch(void* const* d_in, const int* in_sizes, int n_in,
                              void* d_out, int out_size)
{
    const float* input_current = (const float*)d_in[0];
    const float* noise         = (const float*)d_in[1];
    float* out                 = (float*)d_out;

    cudaFuncSetAttribute(TorchLIFNeuronGroup_kernel,
                         cudaFuncAttributeMaxDynamicSharedMemorySize, SMEM_BYTES);

    TorchLIFNeuronGroup_kernel<<<LIF_N / BN, NTHREADS, SMEM_BYTES>>>(
        input_current, noise, out);
}

// round 12
// speedup vs baseline: 1.1767x; 1.1767x over previous
#include <cuda_runtime.h>
#include <cstdint>

// LIF neuron scan: 2048 serial timesteps over 16384 independent neurons.
// R10: R8 structure (all 128 threads issue cp.async + compute) with:
//  - single __syncthreads per chunk (ring slot refilled = slot consumed in the
//    PREVIOUS iteration, so the top-of-loop barrier alone proves reuse safety)
//  - issue-before-compute: next stage's loads go out ahead of the 640-cycle
//    serial compute chain, keeping the in-flight pool topped up
//  - 6-stage ring (192 KB smem) for extra smoothing.

#define LIF_T 2048
#define LIF_N 16384
#define CHUNK 32
#define STAGES 6
#define NCHUNK (LIF_T / CHUNK)          // 64
#define BN 128                           // neurons (and threads) per block
#define STAGE_FLOATS (2 * CHUNK * BN)    // 8192 floats = 32 KB
#define SMEM_BYTES (STAGES * STAGE_FLOATS * 4)  // 192 KB

__device__ __forceinline__ void cp16(float* dst, const float4* src) {
    uint32_t s = (uint32_t)__cvta_generic_to_shared(dst);
    asm volatile("cp.async.cg.shared.global [%0], [%1], 16;\n"
                 :: "r"(s), "l"(src));
}
__device__ __forceinline__ void cp_commit() {
    asm volatile("cp.async.commit_group;\n" ::: "memory");
}
template <int N>
__device__ __forceinline__ void cp_wait() {
    asm volatile("cp.async.wait_group %0;\n" :: "n"(N) : "memory");
}

// Issue one stage's loads: CHUNK rows x 128 neurons for I and Z.
// 2048 float4 thread-ops / 128 threads = 16 cp.async per thread, 1 group.
__device__ __forceinline__ void issue_stage(
    float* __restrict__ smem, int c, int stage,
    const float4* __restrict__ gI4, const float4* __restrict__ gZ4)
{
    float* sI = smem + stage * STAGE_FLOATS;
    float* sZ = sI + CHUNK * BN;
    const int tid = threadIdx.x;
#pragma unroll
    for (int k = 0; k < 8; ++k) {
        const int idx = k * 128 + tid;       // 0..1023
        const int row = idx >> 5;            // 32 float4 per 128-neuron row
        const int col = idx & 31;
        const size_t goff = (size_t)(c * CHUNK + row) * (LIF_N / 4) + col;
        cp16(sI + row * BN + col * 4, gI4 + goff);
        cp16(sZ + row * BN + col * 4, gZ4 + goff);
    }
    cp_commit();
}

__global__ void __launch_bounds__(BN, 1)
TorchLIFNeuronGroup_kernel(const float* __restrict__ gI,
                           const float* __restrict__ gZ,
                           float* __restrict__ gOut)
{
    extern __shared__ float smem[];
    const int tid = threadIdx.x;
    const int n = blockIdx.x * BN + tid;

    const float4* gI4 = (const float4*)(gI + blockIdx.x * BN);
    const float4* gZ4 = (const float4*)(gZ + blockIdx.x * BN);

    // Prologue: fill STAGES-1 slots (slot S-1 stays empty; it's the margin
    // that makes the single-barrier refill safe).
#pragma unroll
    for (int s = 0; s < STAGES - 1; ++s)
        issue_stage(smem, s, s, gI4, gZ4);

    float V = 0.0f;    // V_RESET
    float Vth = 1.0f;  // V_TH0

    for (int c = 0; c < NCHUNK; ++c) {
        const int stage = c % STAGES;

        // Wait until stage c's group is done. Groups issued so far:
        // stages 0 .. min(c + STAGES - 2, NCHUNK - 1); pending allowed after
        // stage c completes = min(STAGES - 2, NCHUNK - 1 - c).
        const int rem = (NCHUNK - 1 - c < STAGES - 2) ? (NCHUNK - 1 - c)
                                                      : (STAGES - 2);
        switch (rem) {
            case 4: cp_wait<4>(); break;
            case 3: cp_wait<3>(); break;
            case 2: cp_wait<2>(); break;
            case 1: cp_wait<1>(); break;
            default: cp_wait<0>(); break;
        }
        // Single barrier: (a) stage c data visible to every thread,
        // (b) every thread finished reading stage c-1 last iteration, so its
        //     slot ((c-1)%STAGES == (c+STAGES-1)%STAGES) may be refilled now.
        __syncthreads();

        // Refill BEFORE compute: keeps loads in flight through the serial chain.
        if (c + STAGES - 1 < NCHUNK)
            issue_stage(smem, c + STAGES - 1, (c + STAGES - 1) % STAGES,
                        gI4, gZ4);

        // Compute CHUNK timesteps (bit-exact body). Scattered __stcs stores
        // are warp-coalesced (consecutive tid -> consecutive addresses) and
        // absorb into the dependency-chain bubbles.
        {
            const float* sI = smem + stage * STAGE_FLOATS + tid;
            const float* sZ = sI + CHUNK * BN;
            float* pO = gOut + (size_t)c * CHUNK * LIF_N + n;
#pragma unroll
            for (int u = 0; u < CHUNK; ++u) {
                const float I  = sI[u * BN];
                const float nz = sZ[u * BN];
                // V = V + (DT/TAU)*(I - V) + noise  (reference op order)
                V = __fmaf_rn(0.05f, I - V, V) + nz;
                const bool sp = (V >= Vth);
                __stcs(pO + (size_t)u * LIF_N, sp ? 1.0f : 0.0f);
                V = sp ? 0.0f : V;
                // Vth starts at 1.0, never decreases -> lower clip is a no-op.
                Vth = sp ? Vth + 0.1f : Vth;
                Vth = fminf(Vth, 2.0f);
            }
        }
    }
}

extern "C" void kernel_launch(void* const* d_in, const int* in_sizes, int n_in,
                              void* d_out, int out_size)
{
    const float* input_current = (const float*)d_in[0];
    const float* noise         = (const float*)d_in[1];
    float* out                 = (float*)d_out;

    cudaFuncSetAttribute(TorchLIFNeuronGroup_kernel,
                         cudaFuncAttributeMaxDynamicSharedMemorySize, SMEM_BYTES);

    TorchLIFNeuronGroup_kernel<<<LIF_N / BN, BN, SMEM_BYTES>>>(
        input_current, noise, out);
}